// round 5
// baseline (speedup 1.0000x reference)
#include <cuda_runtime.h>

// ---------------- problem constants ----------------
#define Bsz   256
#define Cn    7              // bands
#define HWn   16384          // 128*128
#define HID   256
#define SEL   3

#define Mtot  (Bsz*Cn)       // 1792
#define Ktot  HWn            // 16384
#define Ntot  HID            // 256

// ---------------- GEMM tiling ----------------
#define SPLITS 16
#define KC     (Ktot/SPLITS) // 1024
#define BM     64
#define BN     256
#define BK     16

// ---------------- scratch (no allocations allowed) ----------------
__device__ float g_part[SPLITS * (size_t)Mtot * Ntot];  // ~29.4 MB split-K partials
__device__ float g_scores[Mtot];
__device__ int   g_top[Bsz * SEL];

// ---------------- f32x2 helpers (sm_103a packed fp32) ----------------
__device__ __forceinline__ void ffma2(unsigned long long &d,
                                      unsigned long long a,
                                      unsigned long long b) {
    asm("fma.rn.f32x2 %0, %1, %2, %0;" : "+l"(d) : "l"(a), "l"(b));
}
__device__ __forceinline__ unsigned long long pack2(float x) {
    unsigned long long r;
    unsigned int u = __float_as_uint(x);
    asm("mov.b64 %0, {%1, %1};" : "=l"(r) : "r"(u));
    return r;
}
union U64F2 { unsigned long long u; float2 f; };

// ====================================================================
// Kernel 1: split-K fp32 GEMM  C[r, j] = sum_k A[r,k] * W[k,j]
//   A = x viewed as (1792, 16384) row-major,  W = w1 (16384, 256)
//   grid: (Mtot/BM, 1, SPLITS), 256 threads, 8x8 micro-tile via FFMA2
// ====================================================================
__global__ __launch_bounds__(256, 2)
void gemm_kernel(const float* __restrict__ A, const float* __restrict__ W) {
    __shared__ float As[BK][BM];
    __shared__ float Bs[BK][BN];

    const int t     = threadIdx.x;
    const int bm    = blockIdx.x * BM;
    const int split = blockIdx.z;
    const int kb    = split * KC;

    const int ty = t >> 5;   // 0..7  -> rows ty*8..ty*8+7
    const int tx = t & 31;   // 0..31 -> cols tx*8..tx*8+7

    unsigned long long acc[8][4];
    #pragma unroll
    for (int i = 0; i < 8; i++)
        #pragma unroll
        for (int j = 0; j < 4; j++) acc[i][j] = 0ull;

    // A tile loader: 64x16 floats, 1 float4 per thread
    const int arow = t >> 2;            // 0..63
    const int acol = (t & 3) << 2;      // 0,4,8,12
    const float* Ap = A + (size_t)(bm + arow) * Ktot + kb + acol;

    // B tile loader: 16x256 floats, 4 float4 per thread
    const int brow = t >> 6;            // 0..3  (rows brow, brow+4, +8, +12)
    const int bcol = (t & 63) << 2;     // 0..252
    const float* Bp = W + (size_t)(kb + brow) * Ntot + bcol;

    float4 ra  = *(const float4*)Ap;
    float4 rb0 = *(const float4*)(Bp + 0 * 4 * Ntot);
    float4 rb1 = *(const float4*)(Bp + 1 * 4 * Ntot);
    float4 rb2 = *(const float4*)(Bp + 2 * 4 * Ntot);
    float4 rb3 = *(const float4*)(Bp + 3 * 4 * Ntot);

    const int NT = KC / BK;  // 64
    for (int kt = 0; kt < NT; ++kt) {
        // store staged tile (A transposed)
        As[acol + 0][arow] = ra.x;
        As[acol + 1][arow] = ra.y;
        As[acol + 2][arow] = ra.z;
        As[acol + 3][arow] = ra.w;
        *(float4*)&Bs[brow     ][bcol] = rb0;
        *(float4*)&Bs[brow +  4][bcol] = rb1;
        *(float4*)&Bs[brow +  8][bcol] = rb2;
        *(float4*)&Bs[brow + 12][bcol] = rb3;
        __syncthreads();

        // prefetch next tile (overlap gmem latency with compute)
        if (kt + 1 < NT) {
            ra = *(const float4*)(Ap + (kt + 1) * BK);
            const float* Bn = Bp + (size_t)(kt + 1) * BK * Ntot;
            rb0 = *(const float4*)(Bn + 0 * 4 * Ntot);
            rb1 = *(const float4*)(Bn + 1 * 4 * Ntot);
            rb2 = *(const float4*)(Bn + 2 * 4 * Ntot);
            rb3 = *(const float4*)(Bn + 3 * 4 * Ntot);
        }

        #pragma unroll
        for (int k = 0; k < BK; ++k) {
            float4 a0 = *(const float4*)&As[k][ty * 8];
            float4 a1 = *(const float4*)&As[k][ty * 8 + 4];
            ulonglong2 b0 = *(const ulonglong2*)&Bs[k][tx * 8];
            ulonglong2 b1 = *(const ulonglong2*)&Bs[k][tx * 8 + 4];
            unsigned long long aa[8];
            aa[0] = pack2(a0.x); aa[1] = pack2(a0.y);
            aa[2] = pack2(a0.z); aa[3] = pack2(a0.w);
            aa[4] = pack2(a1.x); aa[5] = pack2(a1.y);
            aa[6] = pack2(a1.z); aa[7] = pack2(a1.w);
            #pragma unroll
            for (int i = 0; i < 8; i++) {
                ffma2(acc[i][0], aa[i], b0.x);
                ffma2(acc[i][1], aa[i], b0.y);
                ffma2(acc[i][2], aa[i], b1.x);
                ffma2(acc[i][3], aa[i], b1.y);
            }
        }
        __syncthreads();
    }

    // epilogue -> split-K partials
    float* Cptr = g_part + ((size_t)split * Mtot + bm) * Ntot;
    #pragma unroll
    for (int i = 0; i < 8; i++) {
        const int row = ty * 8 + i;
        U64F2 u0, u1, u2, u3;
        u0.u = acc[i][0]; u1.u = acc[i][1]; u2.u = acc[i][2]; u3.u = acc[i][3];
        float* dst = Cptr + (size_t)row * Ntot + tx * 8;
        *(float4*)(dst)     = make_float4(u0.f.x, u0.f.y, u1.f.x, u1.f.y);
        *(float4*)(dst + 4) = make_float4(u2.f.x, u2.f.y, u3.f.x, u3.f.y);
    }
}

// ====================================================================
// Kernel 2: reduce split-K partials, bias, ReLU, dot with w2 -> score
// one block (256 threads) per (b,c) row; deterministic tree reduction
// ====================================================================
__global__ void score_kernel(const float* __restrict__ b1,
                             const float* __restrict__ w2,
                             const float* __restrict__ b2) {
    const int r = blockIdx.x;
    const int j = threadIdx.x;
    float h = 0.f;
    #pragma unroll
    for (int s = 0; s < SPLITS; s++)
        h += g_part[((size_t)s * Mtot + r) * Ntot + j];
    h += b1[j];
    h = fmaxf(h, 0.f) * w2[j];

    __shared__ float red[256];
    red[j] = h;
    __syncthreads();
    #pragma unroll
    for (int off = 128; off > 0; off >>= 1) {
        if (j < off) red[j] += red[j + off];
        __syncthreads();
    }
    if (j == 0) g_scores[r] = red[0] + b2[0];
}

// ====================================================================
// Kernel 3: stable top-3 of 7 (ties -> lower index, matching lax.top_k)
// one thread per batch element
// ====================================================================
__global__ void topk_kernel(float* __restrict__ out_idx, int write_idx) {
    const int b = threadIdx.x;  // 256 threads, 1 block
    float s[Cn];
    #pragma unroll
    for (int c = 0; c < Cn; c++) s[c] = g_scores[b * Cn + c];
    #pragma unroll
    for (int t = 0; t < SEL; t++) {
        float best = -3.4e38f; int bi = 0;
        #pragma unroll
        for (int c = 0; c < Cn; c++) {
            if (s[c] > best) { best = s[c]; bi = c; }  // strict > keeps lowest index on tie
        }
        g_top[b * SEL + t] = bi;
        s[bi] = -3.4e38f;
        if (write_idx) out_idx[b * SEL + t] = (float)bi;
    }
}

// ====================================================================
// Kernel 4: gather selected bands (B*SEL blocks, 64 KB copy each)
// ====================================================================
__global__ void gather_kernel(const float* __restrict__ x, float* __restrict__ out) {
    const int bs  = blockIdx.x;          // 0..767
    const int b   = bs / SEL;
    const int idx = g_top[bs];
    const float4* src = (const float4*)(x + ((size_t)b * Cn + idx) * HWn);
    float4* dst = (float4*)(out + (size_t)bs * HWn);
    #pragma unroll 4
    for (int i = threadIdx.x; i < HWn / 4; i += 256) dst[i] = src[i];
}

// ====================================================================
extern "C" void kernel_launch(void* const* d_in, const int* in_sizes, int n_in,
                              void* d_out, int out_size) {
    const float* x  = (const float*)d_in[0];
    // d_in[1] = w_qkv, d_in[2] = b_qkv : dead parameters in the reference
    const float* w1 = (const float*)d_in[3];
    const float* b1 = (const float*)d_in[4];
    const float* w2 = (const float*)d_in[5];
    const float* b2 = (const float*)d_in[6];
    float* out = (float*)d_out;

    const long long sel_elems = (long long)Bsz * SEL * HWn;  // 12582912
    const int write_idx = ((long long)out_size >= sel_elems + Bsz * SEL) ? 1 : 0;

    dim3 g1(Mtot / BM, 1, SPLITS);            // 28 x 16 = 448 CTAs
    gemm_kernel<<<g1, 256>>>(x, w1);
    score_kernel<<<Mtot, 256>>>(b1, w2, b2);
    topk_kernel<<<1, Bsz>>>(out + sel_elems, write_idx);
    gather_kernel<<<Bsz * SEL, 256>>>(x, out);
}

// round 7
// speedup vs baseline: 2.1994x; 2.1994x over previous
#include <cuda_runtime.h>
#include <cuda_bf16.h>
#include <cstdint>

// ---------------- problem constants ----------------
#define Bsz   256
#define NBAND 7
#define HWn   16384          // 128*128
#define HID   256
#define SEL   3

#define Mtot  (Bsz*NBAND)    // 1792
#define Ktot  HWn
#define Ntot  HID

// ---------------- GEMM tiling ----------------
#define SPLITS 16
#define KC     (Ktot/SPLITS) // 1024
#define BMt    64
#define BNt    256
#define BKs    32            // K per stage
#define NSTG   (KC/BKs)      // 32

// SMEM layout: padded 80B rows (64B data + 16B pad) -> conflict-free ldmatrix
#define A_VAR  5120          // 64 rows * 80B
#define A_BUF  (2*A_VAR)     // hi+lo
#define B_VAR  20480         // 256 rows * 80B
#define B_BUF  (2*B_VAR)
#define OFFB   (2*A_BUF)     // 20480
#define SMEM_TOTAL (OFFB + 2*B_BUF)   // 102400

// ---------------- scratch ----------------
__device__ float g_part[SPLITS * (size_t)Mtot * Ntot];   // 29.4 MB
__device__ float g_scores[Mtot];
__device__ int   g_top[Bsz * SEL];
__device__ int   g_flag[Bsz];
__device__ __align__(256) __nv_bfloat16 g_wt_hi[(size_t)Ntot * Ktot];  // 8 MB [n][k]
__device__ __align__(256) __nv_bfloat16 g_wt_lo[(size_t)Ntot * Ktot];  // 8 MB

// ---------------- PTX helpers (baseline sm_80 features only) ----------------
__device__ __forceinline__ uint32_t smem_u32(const void* p) {
    uint32_t a;
    asm("{ .reg .u64 t; cvta.to.shared.u64 t, %1; cvt.u32.u64 %0, t; }" : "=r"(a) : "l"(p));
    return a;
}
__device__ __forceinline__ void ldsm4(uint32_t* r, uint32_t addr) {
    asm volatile("ldmatrix.sync.aligned.m8n8.x4.shared.b16 {%0,%1,%2,%3}, [%4];"
                 : "=r"(r[0]), "=r"(r[1]), "=r"(r[2]), "=r"(r[3]) : "r"(addr));
}
__device__ __forceinline__ void mma_bf16(float* c, const uint32_t* a, const uint32_t* b) {
    asm volatile("mma.sync.aligned.m16n8k16.row.col.f32.bf16.bf16.f32 "
                 "{%0,%1,%2,%3}, {%4,%5,%6,%7}, {%8,%9}, {%0,%1,%2,%3};"
                 : "+f"(c[0]), "+f"(c[1]), "+f"(c[2]), "+f"(c[3])
                 : "r"(a[0]), "r"(a[1]), "r"(a[2]), "r"(a[3]), "r"(b[0]), "r"(b[1]));
}
__device__ __forceinline__ void cp16(uint32_t dst, const void* src) {
    uint64_t g = __cvta_generic_to_global(src);
    asm volatile("cp.async.cg.shared.global [%0], [%1], 16;" :: "r"(dst), "l"(g) : "memory");
}
#define CP_COMMIT() asm volatile("cp.async.commit_group;" ::: "memory")
#define CP_WAIT(n)  asm volatile("cp.async.wait_group %0;" :: "n"(n) : "memory")

__device__ __forceinline__ uint32_t pkbf(__nv_bfloat16 a, __nv_bfloat16 b) {
    return ((uint32_t)__bfloat16_as_ushort(b) << 16) | (uint32_t)__bfloat16_as_ushort(a);
}

// ====================================================================
// Kernel 0: transpose + split-convert w1[K][N] -> g_wt_hi/lo [N][K] bf16
// ====================================================================
__global__ void convw_kernel(const float* __restrict__ w1) {
    __shared__ float tl[32][33];
    const int kb = blockIdx.x * 32;
    const int nb = blockIdx.y * 32;
    const int tx = threadIdx.x;   // 0..31
    const int ty = threadIdx.y;   // 0..7
    #pragma unroll
    for (int i = ty; i < 32; i += 8)
        tl[i][tx] = w1[(size_t)(kb + i) * Ntot + nb + tx];
    __syncthreads();
    #pragma unroll
    for (int i = ty; i < 32; i += 8) {
        float v = tl[tx][i];
        __nv_bfloat16 h = __float2bfloat16(v);
        __nv_bfloat16 l = __float2bfloat16(v - __bfloat162float(h));
        size_t o = (size_t)(nb + i) * Ktot + kb + tx;
        g_wt_hi[o] = h;
        g_wt_lo[o] = l;
    }
}

// ====================================================================
// Kernel 1: HMMA bf16 split-accum GEMM (split-K) -> g_part
//   C[r,n] = sum_k x[r,k] * w1[k,n]
//   8 warps: 2(m) x 4(n); warp tile 32x64; mma.m16n8k16
// ====================================================================
__global__ __launch_bounds__(256, 2)
void gemm_kernel(const float* __restrict__ A) {
    extern __shared__ char smem[];
    const uint32_t sb = smem_u32(smem);
    const int tid = threadIdx.x, wid = tid >> 5, lid = tid & 31;
    const int bm    = blockIdx.x * BMt;
    const int split = blockIdx.z;
    const int kbase = split * KC;
    const int wm = wid >> 2, wn = wid & 3;

    float acc[2][8][4];
    #pragma unroll
    for (int i = 0; i < 2; i++)
        #pragma unroll
        for (int j = 0; j < 8; j++)
            #pragma unroll
            for (int q = 0; q < 4; q++) acc[i][j][q] = 0.f;

    const int ar  = tid >> 2;   // A row 0..63
    const int ac  = tid & 3;    // A col segment
    const int bn0 = tid >> 2;   // B row base
    const int bc  = tid & 3;    // B 16B chunk

    const float* Abase = A + (size_t)(bm + ar) * Ktot + kbase;

    auto loadA = [&](int s, float4* r) {
        #pragma unroll
        for (int j = 0; j < 2; j++)
            r[j] = *(const float4*)(Abase + s * BKs + (ac * 2 + j) * 4);
    };
    auto storeA = [&](int s, const float4* r) {
        const int buf = s & 1;
        char* ap = smem + buf * A_BUF + ar * 80;
        #pragma unroll
        for (int j = 0; j < 2; j++) {
            float4 v = r[j];
            __nv_bfloat16 h0 = __float2bfloat16(v.x), h1 = __float2bfloat16(v.y);
            __nv_bfloat16 h2 = __float2bfloat16(v.z), h3 = __float2bfloat16(v.w);
            __nv_bfloat16 l0 = __float2bfloat16(v.x - __bfloat162float(h0));
            __nv_bfloat16 l1 = __float2bfloat16(v.y - __bfloat162float(h1));
            __nv_bfloat16 l2 = __float2bfloat16(v.z - __bfloat162float(h2));
            __nv_bfloat16 l3 = __float2bfloat16(v.w - __bfloat162float(h3));
            const int off = (ac * 2 + j) * 8;
            *(uint2*)(ap + off)         = make_uint2(pkbf(h0, h1), pkbf(h2, h3));
            *(uint2*)(ap + A_VAR + off) = make_uint2(pkbf(l0, l1), pkbf(l2, l3));
        }
    };
    auto loadB = [&](int s) {
        const int buf = s & 1;
        const int k0 = kbase + s * BKs;
        #pragma unroll
        for (int j = 0; j < 4; j++) {
            const int n = j * 64 + bn0;
            const uint32_t dst = sb + OFFB + buf * B_BUF + n * 80 + bc * 16;
            cp16(dst,         g_wt_hi + (size_t)n * Ktot + k0 + bc * 8);
            cp16(dst + B_VAR, g_wt_lo + (size_t)n * Ktot + k0 + bc * 8);
        }
        CP_COMMIT();
    };

    {   // prologue: stages 0 and 1
        float4 r0[2];
        loadA(0, r0); storeA(0, r0); loadB(0);
        loadA(1, r0); storeA(1, r0); loadB(1);
    }

    float4 rn[2];
    #pragma unroll 1
    for (int s = 0; s < NSTG; s++) {
        if (s + 2 < NSTG) loadA(s + 2, rn);
        if (s + 2 < NSTG) { CP_WAIT(1); } else { CP_WAIT(0); }
        __syncthreads();

        const int buf = s & 1;
        const uint32_t aB = sb + buf * A_BUF;
        const uint32_t bB = sb + OFFB + buf * B_BUF;
        #pragma unroll
        for (int kk = 0; kk < 2; kk++) {
            uint32_t ah[2][4], al[2][4];
            #pragma unroll
            for (int mt = 0; mt < 2; mt++) {
                const uint32_t ad = aB +
                    (uint32_t)((wm * 32 + mt * 16 + (lid & 15)) * 80 + kk * 32 + ((lid >> 4) & 1) * 16);
                ldsm4(ah[mt], ad);
                ldsm4(al[mt], ad + A_VAR);
            }
            #pragma unroll
            for (int ng = 0; ng < 4; ng++) {
                const uint32_t bd = bB +
                    (uint32_t)((wn * 64 + ng * 16 + (lid & 7) + ((lid >> 4) & 1) * 8) * 80 +
                               kk * 32 + ((lid >> 3) & 1) * 16);
                uint32_t bh[4], bl[4];
                ldsm4(bh, bd);
                ldsm4(bl, bd + B_VAR);
                #pragma unroll
                for (int mt = 0; mt < 2; mt++) {
                    mma_bf16(acc[mt][2 * ng],     ah[mt], bh);
                    mma_bf16(acc[mt][2 * ng],     ah[mt], bl);
                    mma_bf16(acc[mt][2 * ng],     al[mt], bh);
                    mma_bf16(acc[mt][2 * ng + 1], ah[mt], bh + 2);
                    mma_bf16(acc[mt][2 * ng + 1], ah[mt], bl + 2);
                    mma_bf16(acc[mt][2 * ng + 1], al[mt], bh + 2);
                }
            }
        }
        __syncthreads();
        if (s + 2 < NSTG) { storeA(s + 2, rn); loadB(s + 2); }
    }

    // epilogue: D frag (d0,d1)=(g, 2tg..+1), (d2,d3)=(g+8, 2tg..+1)
    const int g = lid >> 2, tg = lid & 3;
    #pragma unroll
    for (int mt = 0; mt < 2; mt++) {
        const int row0 = bm + wm * 32 + mt * 16 + g;
        #pragma unroll
        for (int nt = 0; nt < 8; nt++) {
            const int col = wn * 64 + nt * 8 + tg * 2;
            float* p0 = g_part + ((size_t)split * Mtot + row0) * Ntot + col;
            float* p1 = g_part + ((size_t)split * Mtot + row0 + 8) * Ntot + col;
            *(float2*)p0 = make_float2(acc[mt][nt][0], acc[mt][nt][1]);
            *(float2*)p1 = make_float2(acc[mt][nt][2], acc[mt][nt][3]);
        }
    }
}

// ====================================================================
// Kernel 2: reduce split-K partials, bias, ReLU, dot w2 -> score
// ====================================================================
__global__ void score_kernel(const float* __restrict__ b1,
                             const float* __restrict__ w2,
                             const float* __restrict__ b2) {
    const int r = blockIdx.x;
    const int j = threadIdx.x;
    float h = 0.f;
    #pragma unroll
    for (int s = 0; s < SPLITS; s++)
        h += g_part[((size_t)s * Mtot + r) * Ntot + j];
    h += b1[j];
    h = fmaxf(h, 0.f) * w2[j];
    __shared__ float red[256];
    red[j] = h;
    __syncthreads();
    #pragma unroll
    for (int off = 128; off > 0; off >>= 1) {
        if (j < off) red[j] += red[j + off];
        __syncthreads();
    }
    if (j == 0) g_scores[r] = red[0] + b2[0];
}

// ====================================================================
// Kernel 3: flag batches whose top-4 gaps are within split error
// ====================================================================
__global__ void gapcheck_kernel() {
    const int b = threadIdx.x;
    float t1 = -3.4e38f, t2 = -3.4e38f, t3 = -3.4e38f, t4 = -3.4e38f;
    #pragma unroll
    for (int c = 0; c < NBAND; c++) {
        float v = g_scores[b * NBAND + c];
        if (v > t1)      { t4 = t3; t3 = t2; t2 = t1; t1 = v; }
        else if (v > t2) { t4 = t3; t3 = t2; t2 = v; }
        else if (v > t3) { t4 = t3; t3 = v; }
        else if (v > t4) { t4 = v; }
    }
    float gp = fminf(t1 - t2, fminf(t2 - t3, t3 - t4));
    g_flag[b] = (gp < 1e-4f) ? 1 : 0;
}

// ====================================================================
// Kernel 4: exact fp32 re-score for flagged batches
// ====================================================================
__global__ void repair_kernel(const float* __restrict__ x, const float* __restrict__ w1,
                              const float* __restrict__ b1v, const float* __restrict__ w2v,
                              const float* __restrict__ b2v) {
    const int r = blockIdx.x;
    if (g_flag[r / NBAND] == 0) return;
    const float* feat = x + (size_t)r * Ktot;
    const int j = threadIdx.x;
    __shared__ float fs[512];
    float h0 = 0.f, h1 = 0.f, h2 = 0.f, h3 = 0.f;
    for (int k0 = 0; k0 < Ktot; k0 += 512) {
        fs[j]       = feat[k0 + j];
        fs[j + 256] = feat[k0 + 256 + j];
        __syncthreads();
        #pragma unroll 4
        for (int k = 0; k < 512; k += 4) {
            h0 = fmaf(fs[k + 0], w1[(size_t)(k0 + k + 0) * Ntot + j], h0);
            h1 = fmaf(fs[k + 1], w1[(size_t)(k0 + k + 1) * Ntot + j], h1);
            h2 = fmaf(fs[k + 2], w1[(size_t)(k0 + k + 2) * Ntot + j], h2);
            h3 = fmaf(fs[k + 3], w1[(size_t)(k0 + k + 3) * Ntot + j], h3);
        }
        __syncthreads();
    }
    float h = ((h0 + h1) + (h2 + h3)) + b1v[j];
    h = fmaxf(h, 0.f) * w2v[j];
    __shared__ float red[256];
    red[j] = h;
    __syncthreads();
    #pragma unroll
    for (int off = 128; off > 0; off >>= 1) {
        if (j < off) red[j] += red[j + off];
        __syncthreads();
    }
    if (j == 0) g_scores[r] = red[0] + b2v[0];
}

// ====================================================================
// Kernel 5: stable top-3 of 7 (ties -> lower index)
// ====================================================================
__global__ void topk_kernel(float* __restrict__ out_idx, int write_idx) {
    const int b = threadIdx.x;
    float s[NBAND];
    #pragma unroll
    for (int c = 0; c < NBAND; c++) s[c] = g_scores[b * NBAND + c];
    #pragma unroll
    for (int t = 0; t < SEL; t++) {
        float best = -3.4e38f; int bi = 0;
        #pragma unroll
        for (int c = 0; c < NBAND; c++)
            if (s[c] > best) { best = s[c]; bi = c; }
        g_top[b * SEL + t] = bi;
        s[bi] = -3.4e38f;
        if (write_idx) out_idx[b * SEL + t] = (float)bi;
    }
}

// ====================================================================
// Kernel 6: gather selected bands
// ====================================================================
__global__ void gather_kernel(const float* __restrict__ x, float* __restrict__ out) {
    const int bs  = blockIdx.x;
    const int b   = bs / SEL;
    const int idx = g_top[bs];
    const float4* src = (const float4*)(x + ((size_t)b * NBAND + idx) * HWn);
    float4* dst = (float4*)(out + (size_t)bs * HWn);
    #pragma unroll 4
    for (int i = threadIdx.x; i < HWn / 4; i += 256) dst[i] = src[i];
}

// ====================================================================
extern "C" void kernel_launch(void* const* d_in, const int* in_sizes, int n_in,
                              void* d_out, int out_size) {
    const float* x  = (const float*)d_in[0];
    const float* w1 = (const float*)d_in[3];
    const float* b1 = (const float*)d_in[4];
    const float* w2 = (const float*)d_in[5];
    const float* b2 = (const float*)d_in[6];
    float* out = (float*)d_out;

    const long long sel_elems = (long long)Bsz * SEL * HWn;
    const int write_idx = ((long long)out_size >= sel_elems + Bsz * SEL) ? 1 : 0;

    cudaFuncSetAttribute(gemm_kernel, cudaFuncAttributeMaxDynamicSharedMemorySize, SMEM_TOTAL);

    dim3 gW(Ktot / 32, Ntot / 32);
    convw_kernel<<<gW, dim3(32, 8)>>>(w1);

    dim3 gG(Mtot / BMt, 1, SPLITS);          // 28 x 16 = 448 CTAs
    gemm_kernel<<<gG, 256, SMEM_TOTAL>>>(x);

    score_kernel<<<Mtot, 256>>>(b1, w2, b2);
    gapcheck_kernel<<<1, Bsz>>>();
    repair_kernel<<<Mtot, 256>>>(x, w1, b1, w2, b2);
    topk_kernel<<<1, Bsz>>>(out + sel_elems, write_idx);
    gather_kernel<<<Bsz * SEL, 256>>>(x, out);
}